// round 8
// baseline (speedup 1.0000x reference)
#include <cuda_runtime.h>
#include <cmath>

#define NB 8
#define LL 1024
#define EE 512

// Scratch (static __device__ arrays per allocation rules)
__device__ float g_proj[4][NB * LL * EE];   // 0=qA, 1=kA, 2=qB, 3=kB   (64 MB)
__device__ float g_scores[32][LL * LL];     // [combo*8 + n][q][k]      (128 MB)

// ---------------- packed f32x2 helpers ----------------
__device__ __forceinline__ unsigned long long dup2(float x) {
    unsigned int u = __float_as_uint(x);
    unsigned long long r;
    asm("mov.b64 %0, {%1, %1};" : "=l"(r) : "r"(u));
    return r;
}
__device__ __forceinline__ unsigned long long ffma2(unsigned long long a,
                                                    unsigned long long b,
                                                    unsigned long long c) {
    unsigned long long d;
    asm("fma.rn.f32x2 %0, %1, %2, %3;" : "=l"(d) : "l"(a), "l"(b), "l"(c));
    return d;
}
__device__ __forceinline__ float2 unpack2(unsigned long long v) {
    unsigned int lo, hi;
    asm("mov.b64 {%0, %1}, %2;" : "=r"(lo), "=r"(hi) : "l"(v));
    return make_float2(__uint_as_float(lo), __uint_as_float(hi));
}

// ---------------- 128x128x512 NT-GEMM tile (C = A * B^T) ----------------
// A: [M][512] row-major, B: [N][512] row-major. M,N multiples of 128.
// blockIdx.y -> M tile, blockIdx.x -> N tile. 256 threads, 8x8 per thread,
// accumulators packed as f32x2 pairs along N.
template <bool HAS_BIAS>
__device__ __forceinline__ void gemm128(const float* __restrict__ A,
                                        const float* __restrict__ B,
                                        float* __restrict__ C, int ldc,
                                        const float* __restrict__ bias,
                                        float scale) {
    __shared__ __align__(16) float As[2][8][128];  // [buf][k][m]
    __shared__ __align__(16) float Bs[2][8][128];  // [buf][k][n]

    const int tid = threadIdx.x;
    const int tx = tid & 15;    // n group (8 cols each)
    const int ty = tid >> 4;    // m group (8 rows each)
    const int m0 = blockIdx.y * 128;
    const int n0 = blockIdx.x * 128;

    // Global load mapping: each thread loads one float4 of A and one of B per chunk.
    const int lrow = tid >> 1;          // 0..127
    const int lk   = (tid & 1) * 4;     // 0 or 4
    const float* ga = A + (size_t)(m0 + lrow) * EE + lk;
    const float* gb = B + (size_t)(n0 + lrow) * EE + lk;

    unsigned long long acc[8][4];
#pragma unroll
    for (int i = 0; i < 8; i++)
#pragma unroll
        for (int j = 0; j < 4; j++) acc[i][j] = 0ULL;

    // prefetch chunk 0 into buffer 0
    {
        float4 va = *(const float4*)ga;
        float4 vb = *(const float4*)gb;
#pragma unroll
        for (int i = 0; i < 4; i++) {
            As[0][lk + i][lrow] = ((const float*)&va)[i];
            Bs[0][lk + i][lrow] = ((const float*)&vb)[i];
        }
    }
    __syncthreads();

    const int NK = EE / 8;  // 64 k-chunks
    for (int kc = 0; kc < NK; kc++) {
        const int buf = kc & 1;
        float4 na, nb;
        if (kc + 1 < NK) {
            na = *(const float4*)(ga + (kc + 1) * 8);
            nb = *(const float4*)(gb + (kc + 1) * 8);
        }
#pragma unroll
        for (int kk = 0; kk < 8; kk++) {
            float4 a0 = *(const float4*)&As[buf][kk][ty * 8];
            float4 a1 = *(const float4*)&As[buf][kk][ty * 8 + 4];
            const ulonglong2 q0 = *(const ulonglong2*)&Bs[buf][kk][tx * 8];
            const ulonglong2 q1 = *(const ulonglong2*)&Bs[buf][kk][tx * 8 + 4];
            unsigned long long b2[4] = {q0.x, q0.y, q1.x, q1.y};
            unsigned long long a2[8];
            a2[0] = dup2(a0.x); a2[1] = dup2(a0.y);
            a2[2] = dup2(a0.z); a2[3] = dup2(a0.w);
            a2[4] = dup2(a1.x); a2[5] = dup2(a1.y);
            a2[6] = dup2(a1.z); a2[7] = dup2(a1.w);
#pragma unroll
            for (int i = 0; i < 8; i++)
#pragma unroll
                for (int j = 0; j < 4; j++)
                    acc[i][j] = ffma2(a2[i], b2[j], acc[i][j]);
        }
        if (kc + 1 < NK) {
#pragma unroll
            for (int i = 0; i < 4; i++) {
                As[buf ^ 1][lk + i][lrow] = ((const float*)&na)[i];
                Bs[buf ^ 1][lk + i][lrow] = ((const float*)&nb)[i];
            }
            __syncthreads();
        }
    }

    // epilogue
#pragma unroll
    for (int i = 0; i < 8; i++) {
        const int m = m0 + ty * 8 + i;
#pragma unroll
        for (int j = 0; j < 4; j++) {
            float2 v = unpack2(acc[i][j]);
            const int n = n0 + tx * 8 + j * 2;
            if (HAS_BIAS) {
                v.x += bias[n];
                v.y += bias[n + 1];
            } else {
                v.x *= scale;
                v.y *= scale;
            }
            *(float2*)&C[(size_t)m * ldc + n] = v;
        }
    }
}

// ---------------- projections: y = x @ W^T + b ----------------
__global__ void __launch_bounds__(256) proj_kernel(
    const float* __restrict__ mA, const float* __restrict__ mB,
    const float* __restrict__ WqA, const float* __restrict__ bqA,
    const float* __restrict__ WkA, const float* __restrict__ bkA,
    const float* __restrict__ WqB, const float* __restrict__ bqB,
    const float* __restrict__ WkB, const float* __restrict__ bkB) {
    const int c = blockIdx.z;
    const float* X;
    const float* W;
    const float* b;
    if (c == 0)      { X = mA; W = WqA; b = bqA; }
    else if (c == 1) { X = mA; W = WkA; b = bkA; }
    else if (c == 2) { X = mB; W = WqB; b = bqB; }
    else             { X = mB; W = WkB; b = bkB; }
    gemm128<true>(X, W, g_proj[c], EE, b, 1.0f);
}

// ---------------- scores: S = q @ k^T * inv_scale ----------------
// combo: 0 = (qA,kA) -> out(0,0), 1 = (qA,kB) -> out(0,1024),
//        2 = (qB,kB) -> out(1024,0), 3 = (qB,kA) -> out(1024,1024)
__global__ void __launch_bounds__(256) score_kernel(float scale) {
    const int z = blockIdx.z;
    const int c = z >> 3;
    const int n = z & 7;
    const int qsel = (c < 2) ? 0 : 2;            // qA or qB
    const int ksel = (c == 0 || c == 3) ? 1 : 3; // kA or kB
    const float* A = g_proj[qsel] + (size_t)n * LL * EE;
    const float* B = g_proj[ksel] + (size_t)n * LL * EE;
    gemm128<false>(A, B, g_scores[z], LL, nullptr, scale);
}

// ---------------- block reductions ----------------
__device__ __forceinline__ float blockReduceMax(float v, float* red) {
#pragma unroll
    for (int o = 16; o > 0; o >>= 1) v = fmaxf(v, __shfl_xor_sync(0xffffffffu, v, o));
    const int w = threadIdx.x >> 5;
    if ((threadIdx.x & 31) == 0) red[w] = v;
    __syncthreads();
    if (threadIdx.x < 8) {
        float t = red[threadIdx.x];
#pragma unroll
        for (int o = 4; o > 0; o >>= 1) t = fmaxf(t, __shfl_xor_sync(0xffu, t, o));
        if (threadIdx.x == 0) red[0] = t;
    }
    __syncthreads();
    v = red[0];
    __syncthreads();
    return v;
}
__device__ __forceinline__ float blockReduceSum(float v, float* red) {
#pragma unroll
    for (int o = 16; o > 0; o >>= 1) v += __shfl_xor_sync(0xffffffffu, v, o);
    const int w = threadIdx.x >> 5;
    if ((threadIdx.x & 31) == 0) red[w] = v;
    __syncthreads();
    if (threadIdx.x < 8) {
        float t = red[threadIdx.x];
#pragma unroll
        for (int o = 4; o > 0; o >>= 1) t += __shfl_xor_sync(0xffu, t, o);
        if (threadIdx.x == 0) red[0] = t;
    }
    __syncthreads();
    v = red[0];
    __syncthreads();
    return v;
}

// ---------------- softmax + mean over N, write [2048,2048] ----------------
__global__ void __launch_bounds__(256) softmax_kernel(float* __restrict__ out) {
    const int q = blockIdx.x;   // 0..1023
    const int c = blockIdx.y;   // 0..3
    const int tid = threadIdx.x;
    __shared__ float red[8];

    float acc0 = 0.f, acc1 = 0.f, acc2 = 0.f, acc3 = 0.f;
    for (int n = 0; n < NB; n++) {
        const float* row = g_scores[c * 8 + n] + (size_t)q * LL;
        const float4 s = *(const float4*)&row[tid * 4];
        float m = fmaxf(fmaxf(s.x, s.y), fmaxf(s.z, s.w));
        m = blockReduceMax(m, red);
        const float e0 = __expf(s.x - m);
        const float e1 = __expf(s.y - m);
        const float e2 = __expf(s.z - m);
        const float e3 = __expf(s.w - m);
        float sum = e0 + e1 + e2 + e3;
        sum = blockReduceSum(sum, red);
        const float r = 1.0f / sum;
        acc0 += e0 * r;
        acc1 += e1 * r;
        acc2 += e2 * r;
        acc3 += e3 * r;
    }
    const int rowBase = (c >= 2) ? 1024 : 0;
    const int colBase = (c == 1 || c == 3) ? 1024 : 0;
    float4 o;
    o.x = acc0 * 0.125f;
    o.y = acc1 * 0.125f;
    o.z = acc2 * 0.125f;
    o.w = acc3 * 0.125f;
    *(float4*)&out[(size_t)(rowBase + q) * 2048 + colBase + tid * 4] = o;
}

// ---------------- launch ----------------
extern "C" void kernel_launch(void* const* d_in, const int* in_sizes, int n_in,
                              void* d_out, int out_size) {
    (void)in_sizes; (void)n_in; (void)out_size;
    const float* mA  = (const float*)d_in[0];
    const float* mB  = (const float*)d_in[1];
    const float* WqA = (const float*)d_in[2];
    const float* bqA = (const float*)d_in[3];
    const float* WkA = (const float*)d_in[4];
    const float* bkA = (const float*)d_in[5];
    const float* WqB = (const float*)d_in[6];
    const float* bqB = (const float*)d_in[7];
    const float* WkB = (const float*)d_in[8];
    const float* bkB = (const float*)d_in[9];
    float* out = (float*)d_out;

    const float inv_scale = 1.0f / (4.0f * sqrtf(512.0f));

    // projections: M=8192, N=512, 4 combos
    proj_kernel<<<dim3(512 / 128, (NB * LL) / 128, 4), 256>>>(
        mA, mB, WqA, bqA, WkA, bkA, WqB, bqB, WkB, bkB);

    // scores: per (combo,n): 1024x1024x512
    score_kernel<<<dim3(LL / 128, LL / 128, 32), 256>>>(inv_scale);

    // softmax rows + mean over N
    softmax_kernel<<<dim3(LL, 4), 256>>>(out);
}

// round 12
// speedup vs baseline: 2.7686x; 2.7686x over previous
#include <cuda_runtime.h>
#include <cmath>
#include <cstdint>

#define NB 8
#define LL 1024
#define EE 512

// ---------------- scratch (static __device__, no allocs) ----------------
__device__ float g_x[2][NB * LL * EE];   // modal A/B, RNA-rounded to tf32
__device__ float g_w[4][EE * EE];        // WqA,WkA,WqB,WkB, RNA-rounded
__device__ float g_p[4][NB * LL * EE];   // proj qA,kA,qB,kB, RNA-rounded
__device__ float g_scores[32][LL * LL];  // [combo*8+n][q][k]

// ---------------- PTX helpers ----------------
__device__ __forceinline__ uint32_t smem_u32(const void* p) {
    uint32_t a;
    asm("{ .reg .u64 t; cvta.to.shared.u64 t, %1; cvt.u32.u64 %0, t; }"
        : "=r"(a) : "l"(p));
    return a;
}
__device__ __forceinline__ uint32_t f2tf32(float x) {
    uint32_t u;
    asm("cvt.rna.tf32.f32 %0, %1;" : "=r"(u) : "f"(x));
    return u;
}
#define CP_ASYNC16(sa, gp) \
    asm volatile("cp.async.cg.shared.global [%0], [%1], 16;" :: "r"(sa), "l"(gp) : "memory")
#define CP_COMMIT() asm volatile("cp.async.commit_group;" ::: "memory")
#define CP_WAIT1()  asm volatile("cp.async.wait_group 1;" ::: "memory")
#define CP_WAIT0()  asm volatile("cp.async.wait_group 0;" ::: "memory")

__device__ __forceinline__ void mma_tf32(float* d, const uint32_t* a,
                                         const uint32_t* b) {
    asm volatile(
        "mma.sync.aligned.m16n8k8.row.col.f32.tf32.tf32.f32 "
        "{%0,%1,%2,%3}, {%4,%5,%6,%7}, {%8,%9}, {%0,%1,%2,%3};"
        : "+f"(d[0]), "+f"(d[1]), "+f"(d[2]), "+f"(d[3])
        : "r"(a[0]), "r"(a[1]), "r"(a[2]), "r"(a[3]), "r"(b[0]), "r"(b[1]));
}

// ---------------- GEMM core: D(128x128,f32) = A(128xK) * B(128xK)^T ------
// A, B row-major fp32 (tf32-valued), K = 512. 256 threads, 8 warps (2m x 4n),
// each warp 64x32 via 4x4 grid of m16n8k8. K-chunk 32, double-buffered cp.async.
#define PITCH 36
#define KC 32
#define FBUF (128 * PITCH)                 // floats per operand per buffer
#define SMEM_SZ (4 * FBUF * 4)             // 73728 bytes

__device__ __forceinline__ void load_chunk(const float* __restrict__ pa,
                                           const float* __restrict__ pb,
                                           int k0, uint32_t sa, uint32_t sb,
                                           int m0, int n0, int tid) {
#pragma unroll
    for (int i = 0; i < 4; i++) {
        const int u = tid + i * 256;
        const int row = u >> 3, seg = u & 7;
        const uint32_t so = (uint32_t)(row * PITCH + seg * 4) * 4u;
        CP_ASYNC16(sa + so, pa + (size_t)(m0 + row) * EE + k0 + seg * 4);
        CP_ASYNC16(sb + so, pb + (size_t)(n0 + row) * EE + k0 + seg * 4);
    }
    CP_COMMIT();
}

// acc layout: acc[mt][nt][4] per PTX m16n8k8 C fragment.
__device__ __forceinline__ void gemm_core(const float* __restrict__ A,
                                          const float* __restrict__ B,
                                          int m0, int n0,
                                          float acc[4][4][4]) {
    extern __shared__ float smem[];
    float* As[2] = {smem, smem + FBUF};
    float* Bs[2] = {smem + 2 * FBUF, smem + 3 * FBUF};
    const uint32_t sAu[2] = {smem_u32(As[0]), smem_u32(As[1])};
    const uint32_t sBu[2] = {smem_u32(Bs[0]), smem_u32(Bs[1])};

    const int tid = threadIdx.x;
    const int lane = tid & 31;
    const int wid = tid >> 5;
    const int wm = (wid & 1) * 64;   // warp m offset in tile
    const int wn = (wid >> 1) * 32;  // warp n offset in tile
    const int g = lane >> 2;         // group id 0..7
    const int c = lane & 3;          // thread-in-group 0..3

#pragma unroll
    for (int mt = 0; mt < 4; mt++)
#pragma unroll
        for (int nt = 0; nt < 4; nt++)
#pragma unroll
            for (int j = 0; j < 4; j++) acc[mt][nt][j] = 0.f;

    load_chunk(A, B, 0, sAu[0], sBu[0], m0, n0, tid);

    const int NCH = EE / KC;  // 16
    for (int ch = 0; ch < NCH; ch++) {
        const int buf = ch & 1;
        if (ch + 1 < NCH)
            load_chunk(A, B, (ch + 1) * KC, sAu[buf ^ 1], sBu[buf ^ 1], m0, n0, tid);
        if (ch + 1 < NCH) { CP_WAIT1(); } else { CP_WAIT0(); }
        __syncthreads();

        const float* sA = As[buf];
        const float* sB = Bs[buf];
#pragma unroll
        for (int ks = 0; ks < KC / 8; ks++) {
            const int k = ks * 8;
            uint32_t af[4][4];
#pragma unroll
            for (int mt = 0; mt < 4; mt++) {
                const float* p = sA + (size_t)(wm + mt * 16 + g) * PITCH + k + c;
                af[mt][0] = __float_as_uint(p[0]);
                af[mt][1] = __float_as_uint(p[8 * PITCH]);
                af[mt][2] = __float_as_uint(p[4]);
                af[mt][3] = __float_as_uint(p[8 * PITCH + 4]);
            }
            uint32_t bf[4][2];
#pragma unroll
            for (int nt = 0; nt < 4; nt++) {
                const float* p = sB + (size_t)(wn + nt * 8 + g) * PITCH + k + c;
                bf[nt][0] = __float_as_uint(p[0]);
                bf[nt][1] = __float_as_uint(p[4]);
            }
#pragma unroll
            for (int mt = 0; mt < 4; mt++)
#pragma unroll
                for (int nt = 0; nt < 4; nt++)
                    mma_tf32(acc[mt][nt], af[mt], bf[nt]);
        }
        __syncthreads();
    }
}

// ---------------- conversion: fp32 -> tf32(RNA)-valued fp32 ----------------
__global__ void __launch_bounds__(256) convert_kernel(
    const float* __restrict__ src, int kind, int idx, int n4) {
    int i = blockIdx.x * blockDim.x + threadIdx.x;
    if (i >= n4) return;
    float* dst = kind ? g_w[idx] : g_x[idx];
    float4 v = ((const float4*)src)[i];
    uint4 o;
    o.x = f2tf32(v.x);
    o.y = f2tf32(v.y);
    o.z = f2tf32(v.z);
    o.w = f2tf32(v.w);
    ((uint4*)dst)[i] = o;
}

// ---------------- projections: q/k = x @ W^T + b ----------------
__global__ void __launch_bounds__(256) proj_mma(
    const float* __restrict__ bqA, const float* __restrict__ bkA,
    const float* __restrict__ bqB, const float* __restrict__ bkB) {
    const int cc = blockIdx.z;
    const int m0 = blockIdx.y * 128, n0 = blockIdx.x * 128;
    const float* bias = (cc == 0) ? bqA : (cc == 1) ? bkA : (cc == 2) ? bqB : bkB;

    float acc[4][4][4];
    gemm_core(g_x[cc >> 1], g_w[cc], m0, n0, acc);

    const int lane = threadIdx.x & 31, wid = threadIdx.x >> 5;
    const int wm = (wid & 1) * 64, wn = (wid >> 1) * 32;
    const int g = lane >> 2, c2 = (lane & 3) * 2;
    float* out = g_p[cc];
#pragma unroll
    for (int nt = 0; nt < 4; nt++) {
        const int n = n0 + wn + nt * 8 + c2;
        const float bv0 = __ldg(&bias[n]);
        const float bv1 = __ldg(&bias[n + 1]);
#pragma unroll
        for (int mt = 0; mt < 4; mt++) {
#pragma unroll
            for (int h = 0; h < 2; h++) {
                const int m = m0 + wm + mt * 16 + h * 8 + g;
                uint2 o;
                o.x = f2tf32(acc[mt][nt][2 * h] + bv0);
                o.y = f2tf32(acc[mt][nt][2 * h + 1] + bv1);
                *(uint2*)&out[(size_t)m * EE + n] = o;
            }
        }
    }
}

// ---------------- scores: S = q @ k^T * inv_scale ----------------
__global__ void __launch_bounds__(256) score_mma(float scale) {
    const int z = blockIdx.z, cc = z >> 3, nn = z & 7;
    const int qsel = (cc < 2) ? 0 : 2;
    const int ksel = (cc == 0 || cc == 3) ? 1 : 3;
    const size_t off = (size_t)nn * LL * EE;
    const int m0 = blockIdx.y * 128, n0 = blockIdx.x * 128;

    float acc[4][4][4];
    gemm_core(g_p[qsel] + off, g_p[ksel] + off, m0, n0, acc);

    const int lane = threadIdx.x & 31, wid = threadIdx.x >> 5;
    const int wm = (wid & 1) * 64, wn = (wid >> 1) * 32;
    const int g = lane >> 2, c2 = (lane & 3) * 2;
    float* out = g_scores[z];
#pragma unroll
    for (int mt = 0; mt < 4; mt++) {
#pragma unroll
        for (int h = 0; h < 2; h++) {
            const int m = m0 + wm + mt * 16 + h * 8 + g;
            float* row = out + (size_t)m * LL;
#pragma unroll
            for (int nt = 0; nt < 4; nt++) {
                float2 v;
                v.x = acc[mt][nt][2 * h] * scale;
                v.y = acc[mt][nt][2 * h + 1] * scale;
                *(float2*)&row[n0 + wn + nt * 8 + c2] = v;
            }
        }
    }
}

// ---------------- block reductions ----------------
__device__ __forceinline__ float blockReduceMax(float v, float* red) {
#pragma unroll
    for (int o = 16; o > 0; o >>= 1) v = fmaxf(v, __shfl_xor_sync(0xffffffffu, v, o));
    const int w = threadIdx.x >> 5;
    if ((threadIdx.x & 31) == 0) red[w] = v;
    __syncthreads();
    if (threadIdx.x < 8) {
        float t = red[threadIdx.x];
#pragma unroll
        for (int o = 4; o > 0; o >>= 1) t = fmaxf(t, __shfl_xor_sync(0xffu, t, o));
        if (threadIdx.x == 0) red[0] = t;
    }
    __syncthreads();
    v = red[0];
    __syncthreads();
    return v;
}
__device__ __forceinline__ float blockReduceSum(float v, float* red) {
#pragma unroll
    for (int o = 16; o > 0; o >>= 1) v += __shfl_xor_sync(0xffffffffu, v, o);
    const int w = threadIdx.x >> 5;
    if ((threadIdx.x & 31) == 0) red[w] = v;
    __syncthreads();
    if (threadIdx.x < 8) {
        float t = red[threadIdx.x];
#pragma unroll
        for (int o = 4; o > 0; o >>= 1) t += __shfl_xor_sync(0xffu, t, o);
        if (threadIdx.x == 0) red[0] = t;
    }
    __syncthreads();
    v = red[0];
    __syncthreads();
    return v;
}

// ---------------- softmax + mean over N, write [2048,2048] ----------------
__global__ void __launch_bounds__(256) softmax_kernel(float* __restrict__ out) {
    const int q = blockIdx.x;
    const int c = blockIdx.y;
    const int tid = threadIdx.x;
    __shared__ float red[8];

    float acc0 = 0.f, acc1 = 0.f, acc2 = 0.f, acc3 = 0.f;
    for (int n = 0; n < NB; n++) {
        const float* row = g_scores[c * 8 + n] + (size_t)q * LL;
        const float4 s = *(const float4*)&row[tid * 4];
        float m = fmaxf(fmaxf(s.x, s.y), fmaxf(s.z, s.w));
        m = blockReduceMax(m, red);
        const float e0 = __expf(s.x - m);
        const float e1 = __expf(s.y - m);
        const float e2 = __expf(s.z - m);
        const float e3 = __expf(s.w - m);
        float sum = e0 + e1 + e2 + e3;
        sum = blockReduceSum(sum, red);
        const float r = 1.0f / sum;
        acc0 += e0 * r; acc1 += e1 * r; acc2 += e2 * r; acc3 += e3 * r;
    }
    const int rowBase = (c >= 2) ? 1024 : 0;
    const int colBase = (c == 1 || c == 3) ? 1024 : 0;
    float4 o;
    o.x = acc0 * 0.125f; o.y = acc1 * 0.125f;
    o.z = acc2 * 0.125f; o.w = acc3 * 0.125f;
    *(float4*)&out[(size_t)(rowBase + q) * 2048 + colBase + tid * 4] = o;
}

// ---------------- launch ----------------
extern "C" void kernel_launch(void* const* d_in, const int* in_sizes, int n_in,
                              void* d_out, int out_size) {
    (void)in_sizes; (void)n_in; (void)out_size;
    const float* mA  = (const float*)d_in[0];
    const float* mB  = (const float*)d_in[1];
    const float* WqA = (const float*)d_in[2];
    const float* bqA = (const float*)d_in[3];
    const float* WkA = (const float*)d_in[4];
    const float* bkA = (const float*)d_in[5];
    const float* WqB = (const float*)d_in[6];
    const float* bqB = (const float*)d_in[7];
    const float* WkB = (const float*)d_in[8];
    const float* bkB = (const float*)d_in[9];
    float* out = (float*)d_out;

    static bool attr_done = false;
    if (!attr_done) {
        cudaFuncSetAttribute(proj_mma,  cudaFuncAttributeMaxDynamicSharedMemorySize, SMEM_SZ);
        cudaFuncSetAttribute(score_mma, cudaFuncAttributeMaxDynamicSharedMemorySize, SMEM_SZ);
        attr_done = true;
    }

    const float inv_scale = 1.0f / (4.0f * sqrtf(512.0f));

    const int n4x = NB * LL * EE / 4;   // 1048576
    const int n4w = EE * EE / 4;        // 65536
    convert_kernel<<<(n4x + 255) / 256, 256>>>(mA,  0, 0, n4x);
    convert_kernel<<<(n4x + 255) / 256, 256>>>(mB,  0, 1, n4x);
    convert_kernel<<<(n4w + 255) / 256, 256>>>(WqA, 1, 0, n4w);
    convert_kernel<<<(n4w + 255) / 256, 256>>>(WkA, 1, 1, n4w);
    convert_kernel<<<(n4w + 255) / 256, 256>>>(WqB, 1, 2, n4w);
    convert_kernel<<<(n4w + 255) / 256, 256>>>(WkB, 1, 3, n4w);

    // projections: 4 combos, M=8192 (64 tiles), N=512 (4 tiles)
    proj_mma<<<dim3(4, 64, 4), 256, SMEM_SZ>>>(bqA, bkA, bqB, bkB);

    // scores: 32 GEMMs of 1024x1024, 8x8 tiles each
    score_mma<<<dim3(8, 8, 32), 256, SMEM_SZ>>>(inv_scale);

    // softmax + mean
    softmax_kernel<<<dim3(LL, 4), 256>>>(out);
}

// round 13
// speedup vs baseline: 2.7951x; 1.0096x over previous
#include <cuda_runtime.h>
#include <cmath>
#include <cstdint>

#define NB 8
#define LL 1024
#define EE 512

// ---------------- scratch (static __device__, no allocs) ----------------
__device__ float g_p[4][NB * LL * EE];   // proj qA,kA,qB,kB (tf32-valued fp32)
__device__ float g_scores[32][LL * LL];  // [combo*8+n][q][k]

// ---------------- PTX helpers ----------------
__device__ __forceinline__ uint32_t smem_u32(const void* p) {
    uint32_t a;
    asm("{ .reg .u64 t; cvta.to.shared.u64 t, %1; cvt.u32.u64 %0, t; }"
        : "=r"(a) : "l"(p));
    return a;
}
__device__ __forceinline__ uint32_t f2tf32(float x) {
    uint32_t u;
    asm("cvt.rna.tf32.f32 %0, %1;" : "=r"(u) : "f"(x));
    return u;
}
#define CP_ASYNC16(sa, gp) \
    asm volatile("cp.async.cg.shared.global [%0], [%1], 16;" :: "r"(sa), "l"(gp) : "memory")
#define CP_COMMIT() asm volatile("cp.async.commit_group;" ::: "memory")
#define CP_WAIT1()  asm volatile("cp.async.wait_group 1;" ::: "memory")
#define CP_WAIT0()  asm volatile("cp.async.wait_group 0;" ::: "memory")

__device__ __forceinline__ void mma_tf32(float* d, const uint32_t* a,
                                         const uint32_t* b) {
    asm volatile(
        "mma.sync.aligned.m16n8k8.row.col.f32.tf32.tf32.f32 "
        "{%0,%1,%2,%3}, {%4,%5,%6,%7}, {%8,%9}, {%0,%1,%2,%3};"
        : "+f"(d[0]), "+f"(d[1]), "+f"(d[2]), "+f"(d[3])
        : "r"(a[0]), "r"(a[1]), "r"(a[2]), "r"(a[3]), "r"(b[0]), "r"(b[1]));
}

// ---------------- GEMM core: D(128x256,f32) = A(128xK) * B(256xK)^T ------
// 256 threads, 8 warps (2m x 4n), each warp 64x64 via 4x8 grid of m16n8k8.
// K = 512, chunk 32, double-buffered cp.async. ROUND: cvt.rna fragments.
#define PITCH 36
#define KC 32
#define AROWS 128
#define BROWS 256
#define FA (AROWS * PITCH)
#define FB (BROWS * PITCH)
#define FBUF (FA + FB)
#define SMEM_SZ (2 * FBUF * 4)   // 110592 bytes

__device__ __forceinline__ void load_chunk(const float* __restrict__ pa,
                                           const float* __restrict__ pb,
                                           int k0, uint32_t sa, uint32_t sb,
                                           int m0, int n0, int tid) {
    // A: units 0..1023 (128 rows x 8 segs); B: units 1024..3071 (256 rows x 8)
#pragma unroll
    for (int i = 0; i < 4; i++) {
        const int u = tid + i * 256;
        const int row = u >> 3, seg = u & 7;
        CP_ASYNC16(sa + (uint32_t)(row * PITCH + seg * 4) * 4u,
                   pa + (size_t)(m0 + row) * EE + k0 + seg * 4);
    }
#pragma unroll
    for (int i = 0; i < 8; i++) {
        const int u = tid + i * 256;
        const int row = u >> 3, seg = u & 7;
        CP_ASYNC16(sb + (uint32_t)(row * PITCH + seg * 4) * 4u,
                   pb + (size_t)(n0 + row) * EE + k0 + seg * 4);
    }
    CP_COMMIT();
}

template <bool ROUND>
__device__ __forceinline__ void gemm_core(const float* __restrict__ A,
                                          const float* __restrict__ B,
                                          int m0, int n0,
                                          float acc[4][8][4]) {
    extern __shared__ float smem[];
    float* As[2] = {smem, smem + FBUF};
    float* Bs[2] = {smem + FA, smem + FBUF + FA};
    const uint32_t sAu[2] = {smem_u32(As[0]), smem_u32(As[1])};
    const uint32_t sBu[2] = {smem_u32(Bs[0]), smem_u32(Bs[1])};

    const int tid = threadIdx.x;
    const int lane = tid & 31;
    const int wid = tid >> 5;
    const int wm = (wid & 1) * 64;   // warp m offset
    const int wn = (wid >> 1) * 64;  // warp n offset
    const int g = lane >> 2;         // group id 0..7
    const int c = lane & 3;          // 0..3

#pragma unroll
    for (int mt = 0; mt < 4; mt++)
#pragma unroll
        for (int nt = 0; nt < 8; nt++)
#pragma unroll
            for (int j = 0; j < 4; j++) acc[mt][nt][j] = 0.f;

    load_chunk(A, B, 0, sAu[0], sBu[0], m0, n0, tid);

    const int NCH = EE / KC;  // 16
    for (int ch = 0; ch < NCH; ch++) {
        const int buf = ch & 1;
        if (ch + 1 < NCH)
            load_chunk(A, B, (ch + 1) * KC, sAu[buf ^ 1], sBu[buf ^ 1], m0, n0, tid);
        if (ch + 1 < NCH) { CP_WAIT1(); } else { CP_WAIT0(); }
        __syncthreads();

        const float* sA = As[buf];
        const float* sB = Bs[buf];
#pragma unroll
        for (int ks = 0; ks < KC / 8; ks++) {
            const int k = ks * 8;
            uint32_t af[4][4];
#pragma unroll
            for (int mt = 0; mt < 4; mt++) {
                const float* p = sA + (size_t)(wm + mt * 16 + g) * PITCH + k + c;
                af[mt][0] = __float_as_uint(p[0]);
                af[mt][1] = __float_as_uint(p[8 * PITCH]);
                af[mt][2] = __float_as_uint(p[4]);
                af[mt][3] = __float_as_uint(p[8 * PITCH + 4]);
                if (ROUND) {
#pragma unroll
                    for (int j = 0; j < 4; j++)
                        af[mt][j] = f2tf32(__uint_as_float(af[mt][j]));
                }
            }
            uint32_t bf[8][2];
#pragma unroll
            for (int nt = 0; nt < 8; nt++) {
                const float* p = sB + (size_t)(wn + nt * 8 + g) * PITCH + k + c;
                bf[nt][0] = __float_as_uint(p[0]);
                bf[nt][1] = __float_as_uint(p[4]);
                if (ROUND) {
                    bf[nt][0] = f2tf32(__uint_as_float(bf[nt][0]));
                    bf[nt][1] = f2tf32(__uint_as_float(bf[nt][1]));
                }
            }
#pragma unroll
            for (int mt = 0; mt < 4; mt++)
#pragma unroll
                for (int nt = 0; nt < 8; nt++)
                    mma_tf32(acc[mt][nt], af[mt], bf[nt]);
        }
        __syncthreads();
    }
}

// ---------------- projections: q/k = x @ W^T + b ----------------
// Reads raw fp32 inputs; rounds fragments to tf32 in-register; writes
// tf32-valued fp32 projections.
__global__ void __launch_bounds__(256) proj_mma(
    const float* __restrict__ mA, const float* __restrict__ mB,
    const float* __restrict__ WqA, const float* __restrict__ bqA,
    const float* __restrict__ WkA, const float* __restrict__ bkA,
    const float* __restrict__ WqB, const float* __restrict__ bqB,
    const float* __restrict__ WkB, const float* __restrict__ bkB) {
    const int cc = blockIdx.z;
    const int m0 = blockIdx.y * 128, n0 = blockIdx.x * 256;
    const float* X = (cc < 2) ? mA : mB;
    const float* W = (cc == 0) ? WqA : (cc == 1) ? WkA : (cc == 2) ? WqB : WkB;
    const float* bias = (cc == 0) ? bqA : (cc == 1) ? bkA : (cc == 2) ? bqB : bkB;

    float acc[4][8][4];
    gemm_core<true>(X, W, m0, n0, acc);

    const int lane = threadIdx.x & 31, wid = threadIdx.x >> 5;
    const int wm = (wid & 1) * 64, wn = (wid >> 1) * 64;
    const int g = lane >> 2, c2 = (lane & 3) * 2;
    float* out = g_p[cc];
#pragma unroll
    for (int nt = 0; nt < 8; nt++) {
        const int n = n0 + wn + nt * 8 + c2;
        const float bv0 = __ldg(&bias[n]);
        const float bv1 = __ldg(&bias[n + 1]);
#pragma unroll
        for (int mt = 0; mt < 4; mt++) {
#pragma unroll
            for (int h = 0; h < 2; h++) {
                const int m = m0 + wm + mt * 16 + h * 8 + g;
                uint2 o;
                o.x = f2tf32(acc[mt][nt][2 * h] + bv0);
                o.y = f2tf32(acc[mt][nt][2 * h + 1] + bv1);
                *(uint2*)&out[(size_t)m * EE + n] = o;
            }
        }
    }
}

// ---------------- scores: S = q @ k^T * inv_scale ----------------
__global__ void __launch_bounds__(256) score_mma(float scale) {
    const int z = blockIdx.z, cc = z >> 3, nn = z & 7;
    const int qsel = (cc < 2) ? 0 : 2;
    const int ksel = (cc == 0 || cc == 3) ? 1 : 3;
    const size_t off = (size_t)nn * LL * EE;
    const int m0 = blockIdx.y * 128, n0 = blockIdx.x * 256;

    float acc[4][8][4];
    gemm_core<false>(g_p[qsel] + off, g_p[ksel] + off, m0, n0, acc);

    const int lane = threadIdx.x & 31, wid = threadIdx.x >> 5;
    const int wm = (wid & 1) * 64, wn = (wid >> 1) * 64;
    const int g = lane >> 2, c2 = (lane & 3) * 2;
    float* out = g_scores[z];
#pragma unroll
    for (int mt = 0; mt < 4; mt++) {
#pragma unroll
        for (int h = 0; h < 2; h++) {
            const int m = m0 + wm + mt * 16 + h * 8 + g;
            float* row = out + (size_t)m * LL;
#pragma unroll
            for (int nt = 0; nt < 8; nt++) {
                float2 v;
                v.x = acc[mt][nt][2 * h] * scale;
                v.y = acc[mt][nt][2 * h + 1] * scale;
                *(float2*)&row[n0 + wn + nt * 8 + c2] = v;
            }
        }
    }
}

// ---------------- block reductions ----------------
__device__ __forceinline__ float blockReduceMax(float v, float* red) {
#pragma unroll
    for (int o = 16; o > 0; o >>= 1) v = fmaxf(v, __shfl_xor_sync(0xffffffffu, v, o));
    const int w = threadIdx.x >> 5;
    if ((threadIdx.x & 31) == 0) red[w] = v;
    __syncthreads();
    if (threadIdx.x < 8) {
        float t = red[threadIdx.x];
#pragma unroll
        for (int o = 4; o > 0; o >>= 1) t = fmaxf(t, __shfl_xor_sync(0xffu, t, o));
        if (threadIdx.x == 0) red[0] = t;
    }
    __syncthreads();
    v = red[0];
    __syncthreads();
    return v;
}
__device__ __forceinline__ float blockReduceSum(float v, float* red) {
#pragma unroll
    for (int o = 16; o > 0; o >>= 1) v += __shfl_xor_sync(0xffffffffu, v, o);
    const int w = threadIdx.x >> 5;
    if ((threadIdx.x & 31) == 0) red[w] = v;
    __syncthreads();
    if (threadIdx.x < 8) {
        float t = red[threadIdx.x];
#pragma unroll
        for (int o = 4; o > 0; o >>= 1) t += __shfl_xor_sync(0xffu, t, o);
        if (threadIdx.x == 0) red[0] = t;
    }
    __syncthreads();
    v = red[0];
    __syncthreads();
    return v;
}

// ---------------- softmax + mean over N, write [2048,2048] ----------------
__global__ void __launch_bounds__(256) softmax_kernel(float* __restrict__ out) {
    const int q = blockIdx.x;
    const int c = blockIdx.y;
    const int tid = threadIdx.x;
    __shared__ float red[8];

    float acc0 = 0.f, acc1 = 0.f, acc2 = 0.f, acc3 = 0.f;
    for (int n = 0; n < NB; n++) {
        const float* row = g_scores[c * 8 + n] + (size_t)q * LL;
        const float4 s = *(const float4*)&row[tid * 4];
        float m = fmaxf(fmaxf(s.x, s.y), fmaxf(s.z, s.w));
        m = blockReduceMax(m, red);
        const float e0 = __expf(s.x - m);
        const float e1 = __expf(s.y - m);
        const float e2 = __expf(s.z - m);
        const float e3 = __expf(s.w - m);
        float sum = e0 + e1 + e2 + e3;
        sum = blockReduceSum(sum, red);
        const float r = 1.0f / sum;
        acc0 += e0 * r; acc1 += e1 * r; acc2 += e2 * r; acc3 += e3 * r;
    }
    const int rowBase = (c >= 2) ? 1024 : 0;
    const int colBase = (c == 1 || c == 3) ? 1024 : 0;
    float4 o;
    o.x = acc0 * 0.125f; o.y = acc1 * 0.125f;
    o.z = acc2 * 0.125f; o.w = acc3 * 0.125f;
    *(float4*)&out[(size_t)(rowBase + q) * 2048 + colBase + tid * 4] = o;
}

// ---------------- launch ----------------
extern "C" void kernel_launch(void* const* d_in, const int* in_sizes, int n_in,
                              void* d_out, int out_size) {
    (void)in_sizes; (void)n_in; (void)out_size;
    const float* mA  = (const float*)d_in[0];
    const float* mB  = (const float*)d_in[1];
    const float* WqA = (const float*)d_in[2];
    const float* bqA = (const float*)d_in[3];
    const float* WkA = (const float*)d_in[4];
    const float* bkA = (const float*)d_in[5];
    const float* WqB = (const float*)d_in[6];
    const float* bqB = (const float*)d_in[7];
    const float* WkB = (const float*)d_in[8];
    const float* bkB = (const float*)d_in[9];
    float* out = (float*)d_out;

    static bool attr_done = false;
    if (!attr_done) {
        cudaFuncSetAttribute(proj_mma,  cudaFuncAttributeMaxDynamicSharedMemorySize, SMEM_SZ);
        cudaFuncSetAttribute(score_mma, cudaFuncAttributeMaxDynamicSharedMemorySize, SMEM_SZ);
        attr_done = true;
    }

    const float inv_scale = 1.0f / (4.0f * sqrtf(512.0f));

    // projections: M=8192 (64 tiles), N=512 (2 tiles of 256), 4 combos
    proj_mma<<<dim3(2, 64, 4), 256, SMEM_SZ>>>(mA, mB, WqA, bqA, WkA, bkA,
                                               WqB, bqB, WkB, bkB);

    // scores: 32 GEMMs of 1024x1024 -> 8 m-tiles x 4 n-tiles each
    score_mma<<<dim3(4, 8, 32), 256, SMEM_SZ>>>(inv_scale);

    // softmax + mean
    softmax_kernel<<<dim3(LL, 4), 256>>>(out);
}